// round 15
// baseline (speedup 1.0000x reference)
#include <cuda_runtime.h>
#include <cuda_bf16.h>
#include <cstdint>
#include <math.h>

#define NE 160000
#define NN 10000
#define CC 64
#define HH 512
#define TLE 32
#define NTHR 256
#define PI_F 3.14159265358979323846f

#define LAT_SB 200
#define HID_SB 520
#define XB_S   72
#define MIX_S  132

// weight quad-slot offsets (uint4 units)
#define Q_EMB2 0
#define Q_V    8192
#define Q_ENV  9216
#define Q_LAT1 11264
#define Q_LAT2 60416
#define Q_MIX  76800
#define TOTQ   80896

__device__ uint4 g_Wq[TOTQ];     // {bh0,bh1,bl0,bl1} bf16x2 fragment quads
__device__ float g_x[NE * CC];
__device__ float g_u[NE * 3];
__device__ float g_env[NE];
__device__ float g_V[NE * CC * 3];
__device__ float g_rho0a[NN * CC];
__device__ float g_rho1a[NN * CC * 3];
__device__ float g_rho0b[NN * CC];
__device__ float g_rho1b[NN * CC * 3];

__device__ __forceinline__ float silu_f(float v) { return v / (1.f + __expf(-v)); }

__device__ __forceinline__ void mma16(float c[4], uint32_t a0, uint32_t a1, uint32_t a2,
                                      uint32_t a3, uint32_t b0, uint32_t b1) {
    asm volatile(
        "mma.sync.aligned.m16n8k16.row.col.f32.bf16.bf16.f32 "
        "{%0,%1,%2,%3},{%4,%5,%6,%7},{%8,%9},{%0,%1,%2,%3};\n"
        : "+f"(c[0]), "+f"(c[1]), "+f"(c[2]), "+f"(c[3])
        : "r"(a0), "r"(a1), "r"(a2), "r"(a3), "r"(b0), "r"(b1));
}

__device__ __forceinline__ void bfsplit(float v, uint16_t& h, uint16_t& l) {
    __nv_bfloat16 hb = __float2bfloat16_rn(v);
    float hf = __bfloat162float(hb);
    __nv_bfloat16 lb = __float2bfloat16_rn(v - hf);
    h = *reinterpret_cast<uint16_t*>(&hb);
    l = *reinterpret_cast<uint16_t*>(&lb);
}
__device__ __forceinline__ float bf2f(uint16_t u) {
    return __uint_as_float(((uint32_t)u) << 16);
}

__device__ __forceinline__ uint32_t cvta_s(const void* p) {
    return (uint32_t)__cvta_generic_to_shared(p);
}
__device__ __forceinline__ void ldsm_x4(uint32_t a[4], uint32_t addr) {
    asm volatile("ldmatrix.sync.aligned.m8n8.x4.shared.b16 {%0,%1,%2,%3}, [%4];"
                 : "=r"(a[0]), "=r"(a[1]), "=r"(a[2]), "=r"(a[3]) : "r"(addr));
}
__device__ __forceinline__ uint32_t ldsm_base16(const uint16_t* sA, int lda, int rb, int lane) {
    int m = lane >> 3, r = lane & 7;
    int row = rb + r + ((m & 1) << 3);
    int coff = (m >> 1) << 3;
    return cvta_s(&sA[row * lda + coff]);
}

// ============================================================
// split-bf16 3-term GEMM: ah*bh + ah*bl + al*bh
// ============================================================
template <int MT, int NT, int KS>
__device__ __forceinline__ void gemm4(const uint16_t* sAhi, const uint16_t* sAlo,
                                      int lda, int r0,
                                      const uint4* __restrict__ Bq,
                                      int ldb, int n0, int g, int t, int lane,
                                      float (&acc)[MT][NT][4]) {
    #pragma unroll
    for (int m = 0; m < MT; m++)
        #pragma unroll
        for (int j = 0; j < NT; j++)
            #pragma unroll
            for (int q = 0; q < 4; q++) acc[m][j][q] = 0.f;

    uint32_t bah[MT], bal[MT];
    #pragma unroll
    for (int m = 0; m < MT; m++) {
        bah[m] = ldsm_base16(sAhi, lda, r0 + 16 * m, lane);
        bal[m] = ldsm_base16(sAlo, lda, r0 + 16 * m, lane);
    }
    const uint4* __restrict__ Bbase = Bq + (n0 + g) * 4 + t;

    #pragma unroll 4
    for (int ks = 0; ks < KS; ks++) {
        uint32_t Ah[MT][4], Al[MT][4];
        #pragma unroll
        for (int m = 0; m < MT; m++) {
            ldsm_x4(Ah[m], bah[m] + ks * 32);
            ldsm_x4(Al[m], bal[m] + ks * 32);
        }
        const uint4* __restrict__ Brow = Bbase + ks * ldb * 4;
        #pragma unroll
        for (int j = 0; j < NT; j++) {
            uint4 B = __ldg(Brow + j * 32);
            #pragma unroll
            for (int m = 0; m < MT; m++) {
                mma16(acc[m][j], Ah[m][0], Ah[m][1], Ah[m][2], Ah[m][3], B.x, B.y);
                mma16(acc[m][j], Ah[m][0], Ah[m][1], Ah[m][2], Ah[m][3], B.z, B.w);
                mma16(acc[m][j], Al[m][0], Al[m][1], Al[m][2], Al[m][3], B.x, B.y);
            }
        }
    }
}

// ============================================================
__global__ void k_zero(float* __restrict__ out) {
    int idx = blockIdx.x * 256 + threadIdx.x;
    if (idx < NN) out[idx] = 0.f;
    if (idx < NN * CC) { g_rho0a[idx] = 0.f; g_rho0b[idx] = 0.f; }
    if (idx < NN * CC * 3) { g_rho1a[idx] = 0.f; g_rho1b[idx] = 0.f; }
}

__global__ void k_prep(const float* __restrict__ emb2, const float* __restrict__ wv,
                       const float* __restrict__ wenv, const float* __restrict__ lat1,
                       const float* __restrict__ lat2, const float* __restrict__ wmix) {
    int s = blockIdx.x * 256 + threadIdx.x;
    if (s >= TOTQ) return;
    const float* src; int base, rows, ldb;
    if (s < Q_V)         { src = emb2; base = Q_EMB2; rows = 512; ldb = 64; }
    else if (s < Q_ENV)  { src = wv;   base = Q_V;    rows = 64;  ldb = 64; }
    else if (s < Q_LAT1) { src = wenv; base = Q_ENV;  rows = 64;  ldb = 64; }
    else if (s < Q_LAT2) { src = lat1; base = Q_LAT1; rows = 192; ldb = 512; }
    else if (s < Q_MIX)  { src = lat2; base = Q_LAT2; rows = 512; ldb = 64; }
    else                 { src = wmix; base = Q_MIX;  rows = 64;  ldb = 128; }
    int sl = s - base;
    int mslots = rows * ldb / 4;
    int m = sl / mslots; sl -= m * mslots;
    int t = sl & 3; int tmp = sl >> 2;
    int col = tmp % ldb, kc = tmp / ldb;
    const float* M = src + m * rows * ldb;
    int k0 = kc * 16 + 2 * t;
    float v0 = M[k0 * ldb + col],       v1 = M[(k0 + 1) * ldb + col];
    float v2 = M[(k0 + 8) * ldb + col], v3 = M[(k0 + 9) * ldb + col];
    uint16_t h0, l0, h1, l1, h2, l2, h3, l3;
    bfsplit(v0, h0, l0); bfsplit(v1, h1, l1);
    bfsplit(v2, h2, l2); bfsplit(v3, h3, l3);
    g_Wq[s] = make_uint4(((uint32_t)h1 << 16) | h0, ((uint32_t)h3 << 16) | h2,
                         ((uint32_t)l1 << 16) | l0, ((uint32_t)l3 << 16) | l2);
}

// ============================================================
// K1: embed — 32 edges/block, 256 threads, 2 blocks/SM
// ============================================================
__global__ __launch_bounds__(NTHR, 2) void k_embed(
    const float* __restrict__ pos,
    const int* __restrict__ species,
    const int* __restrict__ senders,
    const int* __restrict__ receivers,
    const float* __restrict__ W1)    // [12,512] fp32
{
    extern __shared__ uint16_t smu[];
    uint16_t* s_hhi = smu;                       // [32][HID_SB]
    uint16_t* s_hlo = s_hhi + TLE * HID_SB;
    uint16_t* s_xhi = s_hlo + TLE * HID_SB;      // [32][XB_S]
    uint16_t* s_xlo = s_xhi + TLE * XB_S;
    __shared__ float s_feat[TLE][13];
    __shared__ float s_env[TLE];
    __shared__ float s_u3[TLE * 3];
    __shared__ int   s_send[TLE];

    const int tid = threadIdx.x;
    const int warp = tid >> 5, lane = tid & 31;
    const int g = lane >> 2, t = lane & 3;
    const int e0 = blockIdx.x * TLE;

    if (tid < TLE) {
        int e = e0 + tid;
        int sn = senders[e], rc = receivers[e];
        s_send[tid] = sn;
        float rx = pos[rc * 3 + 0] - pos[sn * 3 + 0];
        float ry = pos[rc * 3 + 1] - pos[sn * 3 + 1];
        float rz = pos[rc * 3 + 2] - pos[sn * 3 + 2];
        float d = sqrtf(rx * rx + ry * ry + rz * rz);
        float ds = fmaxf(d, 1e-6f);
        float inv = 1.f / ds;
        float ux = rx * inv, uy = ry * inv, uz = rz * inv;
        g_u[e * 3 + 0] = ux; g_u[e * 3 + 1] = uy; g_u[e * 3 + 2] = uz;
        s_u3[tid * 3 + 0] = ux; s_u3[tid * 3 + 1] = uy; s_u3[tid * 3 + 2] = uz;
        float xc = d * 0.5f;
        float env = 0.f;
        if (xc < 1.f) { float tt = 1.f - xc * xc; env = tt * tt; }
        g_env[e] = env;
        s_env[tid] = env;
        float pref = env * inv;
        float ang = PI_F * xc;
        #pragma unroll
        for (int n = 1; n <= 8; n++) s_feat[tid][n - 1] = pref * __sinf((float)n * ang);
        float ssn = (species[sn] == 1) ? 1.f : 0.f;
        float src = (species[rc] == 1) ? 1.f : 0.f;
        s_feat[tid][8] = 1.f - ssn; s_feat[tid][9] = ssn;
        s_feat[tid][10] = 1.f - src; s_feat[tid][11] = src;
    }
    __syncthreads();

    // phase A: hidden = silu(feat @ W1)  (K=12 scalar), 2 cols/thread
    #pragma unroll
    for (int jj = 0; jj < 2; jj++) {
        int h = tid + 256 * jj;
        float w1r[12];
        #pragma unroll
        for (int k = 0; k < 12; k++) w1r[k] = W1[k * HH + h];
        #pragma unroll 4
        for (int i = 0; i < TLE; i++) {
            float acc = 0.f;
            #pragma unroll
            for (int k = 0; k < 12; k++) acc += s_feat[i][k] * w1r[k];
            uint16_t hh, ll;
            bfsplit(silu_f(acc), hh, ll);
            s_hhi[i * HID_SB + h] = hh;
            s_hlo[i * HID_SB + h] = ll;
        }
    }
    __syncthreads();

    // phase B: x = (hidden @ W_emb2) * env
    {
        float a2[2][1][4];
        int n0 = warp * 8;
        gemm4<2, 1, 32>(s_hhi, s_hlo, HID_SB, 0, g_Wq + Q_EMB2, CC, n0, g, t, lane, a2);
        #pragma unroll
        for (int m = 0; m < 2; m++)
            #pragma unroll
            for (int q = 0; q < 4; q++) {
                int r = m * 16 + g + ((q & 2) ? 8 : 0);
                int c = n0 + 2 * t + (q & 1);
                float x = a2[m][0][q] * s_env[r];
                g_x[(e0 + r) * CC + c] = x;
                uint16_t hh, ll;
                bfsplit(x, hh, ll);
                s_xhi[r * XB_S + c] = hh;
                s_xlo[r * XB_S + c] = ll;
            }
    }
    __syncthreads();

    // vinit: V = (x @ Wv) outer u
    {
        float av[2][1][4];
        int n0 = warp * 8;
        gemm4<2, 1, 4>(s_xhi, s_xlo, XB_S, 0, g_Wq + Q_V, CC, n0, g, t, lane, av);
        #pragma unroll
        for (int m = 0; m < 2; m++)
            #pragma unroll
            for (int q = 0; q < 4; q++) {
                int r = m * 16 + g + ((q & 2) ? 8 : 0);
                int c = n0 + 2 * t + (q & 1);
                float v = av[m][0][q];
                int vb = ((e0 + r) * CC + c) * 3;
                g_V[vb + 0] = v * s_u3[r * 3 + 0];
                g_V[vb + 1] = v * s_u3[r * 3 + 1];
                g_V[vb + 2] = v * s_u3[r * 3 + 2];
            }
    }

    // scatter layer-0 density
    {
        float as[2][1][4];
        int n0 = warp * 8;
        gemm4<2, 1, 4>(s_xhi, s_xlo, XB_S, 0, g_Wq + Q_ENV, CC, n0, g, t, lane, as);
        #pragma unroll
        for (int m = 0; m < 2; m++)
            #pragma unroll
            for (int q = 0; q < 4; q++) {
                int r = m * 16 + g + ((q & 2) ? 8 : 0);
                int c = n0 + 2 * t + (q & 1);
                float v = as[m][0][q] * (1.f / 3.f);
                int sn = s_send[r];
                atomicAdd(&g_rho0a[sn * CC + c], v);
                int rb = (sn * CC + c) * 3;
                atomicAdd(&g_rho1a[rb + 0], v * s_u3[r * 3 + 0]);
                atomicAdd(&g_rho1a[rb + 1], v * s_u3[r * 3 + 1]);
                atomicAdd(&g_rho1a[rb + 2], v * s_u3[r * 3 + 2]);
            }
    }
}

// ============================================================
// K2: full layer — 32 edges/block, 256 threads, 3 blocks/SM
// half-hidden pipeline (16-row hidden buffer)
// ============================================================
__global__ __launch_bounds__(NTHR, 3) void k_layer(
    int loff1, int loff2, int loffm, int loffe,
    const float* __restrict__ Wout,
    const int* __restrict__ senders,
    const int* __restrict__ receivers,
    const float* __restrict__ rho0r,
    const float* __restrict__ rho1r,
    float* __restrict__ rho0w,
    float* __restrict__ rho1w,
    float* __restrict__ out,
    int mode)
{
    extern __shared__ uint16_t smu[];
    uint16_t* s_lhi = smu;                       // [32][LAT_SB]
    uint16_t* s_llo = s_lhi + TLE * LAT_SB;
    uint16_t* s_hhi = s_llo + TLE * LAT_SB;      // [16][HID_SB] half buffer
    uint16_t* s_hlo = s_hhi + 16 * HID_SB;
    float* s_mix = reinterpret_cast<float*>(s_hhi);  // overlay after phase2 ([32][MIX_S] fl = 16.9KB <= 33.3KB)
    __shared__ int   s_send[TLE], s_recv[TLE];
    __shared__ float s_env[TLE], s_u3[TLE * 3];

    const int tid = threadIdx.x;
    const int warp = tid >> 5, lane = tid & 31;
    const int g = lane >> 2, t = lane & 3;
    const int e0 = blockIdx.x * TLE;

    if (tid < TLE) {
        int e = e0 + tid;
        s_send[tid] = senders[e];
        s_recv[tid] = receivers[e];
        s_env[tid] = g_env[e];
        s_u3[tid * 3 + 0] = g_u[e * 3 + 0];
        s_u3[tid * 3 + 1] = g_u[e * 3 + 1];
        s_u3[tid * 3 + 2] = g_u[e * 3 + 2];
    }
    __syncthreads();

    // ---- build split lat_in = [x | tp_scal | rho0_e] ----
    #pragma unroll
    for (int q = 0; q < (TLE * CC) / NTHR; q++) {
        int idx = tid + NTHR * q;
        int i = idx >> 6, c = idx & 63;
        int e = e0 + i, sn = s_send[i];
        float xv = g_x[e * CC + c];
        float r0v = rho0r[sn * CC + c];
        int rb = (sn * CC + c) * 3;
        float r1x = rho1r[rb], r1y = rho1r[rb + 1], r1z = rho1r[rb + 2];
        int vb = (e * CC + c) * 3;
        float Vx = g_V[vb], Vy = g_V[vb + 1], Vz = g_V[vb + 2];
        float tp = Vx * r1x + Vy * r1y + Vz * r1z;
        uint16_t h0, l0, h1, l1, h2, l2;
        bfsplit(xv, h0, l0); bfsplit(tp, h1, l1); bfsplit(r0v, h2, l2);
        s_lhi[i * LAT_SB + c]       = h0;  s_llo[i * LAT_SB + c]       = l0;
        s_lhi[i * LAT_SB + 64 + c]  = h1;  s_llo[i * LAT_SB + 64 + c]  = l1;
        s_lhi[i * LAT_SB + 128 + c] = h2;  s_llo[i * LAT_SB + 128 + c] = l2;
    }
    __syncthreads();

    // ---- two-half hidden pipeline ----
    const float inv_s2 = 0.70710678118654752f;
    #pragma unroll 1
    for (int half = 0; half < 2; half++) {
        const int hr0 = half * 16;

        // phase 1: hidden[16 rows local] = silu(lat rows hr0.. @ W1); MT=1 NT=8
        {
            float c1[1][8][4];
            int n0 = warp * 64;
            gemm4<1, 8, 12>(s_lhi, s_llo, LAT_SB, hr0, g_Wq + loff1, HH, n0, g, t, lane, c1);
            #pragma unroll
            for (int j = 0; j < 8; j++)
                #pragma unroll
                for (int q = 0; q < 4; q++) {
                    int r = g + ((q & 2) ? 8 : 0);        // local row 0..15
                    int c = n0 + 8 * j + 2 * t + (q & 1);
                    uint16_t hh, ll;
                    bfsplit(silu_f(c1[0][j][q]), hh, ll);
                    s_hhi[r * HID_SB + c] = hh;
                    s_hlo[r * HID_SB + c] = ll;
                }
        }
        __syncthreads();

        // phase 2: dx = hidden @ W2 ; x update (rows hr0..hr0+15); MT=1
        {
            float a2[1][1][4];
            int n0 = warp * 8;
            gemm4<1, 1, 32>(s_hhi, s_hlo, HID_SB, 0, g_Wq + loff2, CC, n0, g, t, lane, a2);
            #pragma unroll
            for (int q = 0; q < 4; q++) {
                int rl = g + ((q & 2) ? 8 : 0);
                int r = hr0 + rl;
                int c = n0 + 2 * t + (q & 1);
                float xo = bf2f(s_lhi[r * LAT_SB + c]) + bf2f(s_llo[r * LAT_SB + c]);
                float xn = (xo + a2[0][0][q] * s_env[r]) * inv_s2;
                g_x[(e0 + r) * CC + c] = xn;
                uint16_t hh, ll;
                bfsplit(xn, hh, ll);
                s_lhi[r * LAT_SB + c] = hh;
                s_llo[r * LAT_SB + c] = ll;
            }
        }
        __syncthreads();
    }

    if (mode == 0) {
        // ---- phase 3a: mix = x_new @ Wm (N=128: 8 warps x 16 cols), MT=2 ----
        {
            float am[2][2][4];
            int n0 = warp * 16;
            gemm4<2, 2, 4>(s_lhi, s_llo, LAT_SB, 0, g_Wq + loffm, 2 * CC, n0, g, t, lane, am);
            __syncthreads();   // s_mix overlays s_hhi
            #pragma unroll
            for (int m = 0; m < 2; m++)
                #pragma unroll
                for (int j = 0; j < 2; j++)
                    #pragma unroll
                    for (int q = 0; q < 4; q++) {
                        int r = m * 16 + g + ((q & 2) ? 8 : 0);
                        int c = n0 + 8 * j + 2 * t + (q & 1);
                        s_mix[r * MIX_S + c] = am[m][j][q];
                    }
        }
        __syncthreads();

        // ---- phase 3b: V = mix1 * (V * rho0) + mix2 * cross(V, rho1) ----
        #pragma unroll
        for (int q = 0; q < (TLE * CC) / NTHR; q++) {
            int idx = tid + NTHR * q;
            int i = idx >> 6, c = idx & 63;
            int e = e0 + i, sn = s_send[i];
            int vb = (e * CC + c) * 3;
            float Vx = g_V[vb], Vy = g_V[vb + 1], Vz = g_V[vb + 2];
            int rb = (sn * CC + c) * 3;
            float r1x = rho1r[rb], r1y = rho1r[rb + 1], r1z = rho1r[rb + 2];
            float r0v = bf2f(s_lhi[i * LAT_SB + 128 + c]) + bf2f(s_llo[i * LAT_SB + 128 + c]);
            float m1 = s_mix[i * MIX_S + c];
            float m2 = s_mix[i * MIX_S + 64 + c];
            float cx = Vy * r1z - Vz * r1y;
            float cy = Vz * r1x - Vx * r1z;
            float cz = Vx * r1y - Vy * r1x;
            g_V[vb + 0] = m1 * Vx * r0v + m2 * cx;
            g_V[vb + 1] = m1 * Vy * r0v + m2 * cy;
            g_V[vb + 2] = m1 * Vz * r0v + m2 * cz;
        }

        // ---- scatter next-layer density (uses x_new) ----
        {
            float as[2][1][4];
            int n0 = warp * 8;
            gemm4<2, 1, 4>(s_lhi, s_llo, LAT_SB, 0, g_Wq + loffe, CC, n0, g, t, lane, as);
            #pragma unroll
            for (int m = 0; m < 2; m++)
                #pragma unroll
                for (int q = 0; q < 4; q++) {
                    int r = m * 16 + g + ((q & 2) ? 8 : 0);
                    int c = n0 + 2 * t + (q & 1);
                    float v = as[m][0][q] * (1.f / 3.f);
                    int sn = s_send[r];
                    atomicAdd(&rho0w[sn * CC + c], v);
                    int rb = (sn * CC + c) * 3;
                    atomicAdd(&rho1w[rb + 0], v * s_u3[r * 3 + 0]);
                    atomicAdd(&rho1w[rb + 1], v * s_u3[r * 3 + 1]);
                    atomicAdd(&rho1w[rb + 2], v * s_u3[r * 3 + 2]);
                }
        }
    } else {
        // ---- final energy readout: 256 threads, 8/row ----
        int i = tid >> 3, k8 = tid & 7;
        float p = 0.f;
        #pragma unroll
        for (int q = 0; q < 8; q++) {
            int c = k8 + 8 * q;
            p += (bf2f(s_lhi[i * LAT_SB + c]) + bf2f(s_llo[i * LAT_SB + c]))
                 * __ldg(&Wout[c]);
        }
        p += __shfl_xor_sync(0xffffffffu, p, 1);
        p += __shfl_xor_sync(0xffffffffu, p, 2);
        p += __shfl_xor_sync(0xffffffffu, p, 4);
        if ((tid & 7) == 0)
            atomicAdd(&out[s_recv[i]], p * s_env[i] * (1.f / 3.f));
    }
}

// ============================================================
extern "C" void kernel_launch(void* const* d_in, const int* in_sizes, int n_in,
                              void* d_out, int out_size)
{
    const float* pos     = (const float*)d_in[0];
    const float* W_emb1  = (const float*)d_in[1];
    const float* W_emb2  = (const float*)d_in[2];
    const float* W_v     = (const float*)d_in[3];
    const float* W_env   = (const float*)d_in[4];
    const float* W_lat1  = (const float*)d_in[5];
    const float* W_lat2  = (const float*)d_in[6];
    const float* W_mix   = (const float*)d_in[7];
    const float* W_out   = (const float*)d_in[8];
    const int*   species = (const int*)d_in[9];
    const int*   senders = (const int*)d_in[10];
    const int*   recv    = (const int*)d_in[11];
    float* out = (float*)d_out;

    const int smem_embed = (2 * TLE * HID_SB + 2 * TLE * XB_S) * 2;   // 75776
    const int smem_layer = (2 * TLE * LAT_SB + 2 * 16 * HID_SB) * 2;  // 58880
    cudaFuncSetAttribute(k_embed, cudaFuncAttributeMaxDynamicSharedMemorySize, smem_embed);
    cudaFuncSetAttribute(k_layer, cudaFuncAttributeMaxDynamicSharedMemorySize, smem_layer);

    float* rho0a; cudaGetSymbolAddress((void**)&rho0a, g_rho0a);
    float* rho1a; cudaGetSymbolAddress((void**)&rho1a, g_rho1a);
    float* rho0b; cudaGetSymbolAddress((void**)&rho0b, g_rho0b);
    float* rho1b; cudaGetSymbolAddress((void**)&rho1b, g_rho1b);

    k_zero<<<(NN * CC * 3 + 255) / 256, 256>>>(out);
    k_prep<<<(TOTQ + 255) / 256, 256>>>(W_emb2, W_v, W_env, W_lat1, W_lat2, W_mix);
    k_embed<<<NE / TLE, NTHR, smem_embed>>>(pos, species, senders, recv, W_emb1);

    // layer 0: read rhoA, scatter rhoB for layer 1
    k_layer<<<NE / TLE, NTHR, smem_layer>>>(
        Q_LAT1, Q_LAT2, Q_MIX, Q_ENV + 1024, nullptr,
        senders, recv, rho0a, rho1a, rho0b, rho1b, out, 0);
    // layer 1 (final): read rhoB, energy readout
    k_layer<<<NE / TLE, NTHR, smem_layer>>>(
        Q_LAT1 + 24576, Q_LAT2 + 8192, Q_MIX + 2048, 0, W_out,
        senders, recv, rho0b, rho1b, nullptr, nullptr, out, 1);
}

// round 16
// speedup vs baseline: 1.0352x; 1.0352x over previous
#include <cuda_runtime.h>
#include <cuda_bf16.h>
#include <cstdint>
#include <math.h>

#define NE 160000
#define NN 10000
#define CC 64
#define HH 512
#define TLE 32
#define NTHR 256
#define PI_F 3.14159265358979323846f

#define LAT_SB 200
#define HID_SB 520
#define XB_S   72
#define MIX_S  132
#define DX_S   68

// weight quad-slot offsets (uint4 units)
#define Q_EMB2 0
#define Q_V    8192
#define Q_ENV  9216
#define Q_LAT1 11264
#define Q_LAT2 60416
#define Q_MIX  76800
#define TOTQ   80896

__device__ uint4 g_Wq[TOTQ];     // {bh0,bh1,bl0,bl1} bf16x2 fragment quads
__device__ float g_x[NE * CC];
__device__ float g_u[NE * 3];
__device__ float g_env[NE];
__device__ float g_V[NE * CC * 3];
__device__ float g_rho0a[NN * CC];
__device__ float g_rho1a[NN * CC * 3];
__device__ float g_rho0b[NN * CC];
__device__ float g_rho1b[NN * CC * 3];

__device__ __forceinline__ float silu_f(float v) { return v / (1.f + __expf(-v)); }

__device__ __forceinline__ void mma16(float c[4], uint32_t a0, uint32_t a1, uint32_t a2,
                                      uint32_t a3, uint32_t b0, uint32_t b1) {
    asm volatile(
        "mma.sync.aligned.m16n8k16.row.col.f32.bf16.bf16.f32 "
        "{%0,%1,%2,%3},{%4,%5,%6,%7},{%8,%9},{%0,%1,%2,%3};\n"
        : "+f"(c[0]), "+f"(c[1]), "+f"(c[2]), "+f"(c[3])
        : "r"(a0), "r"(a1), "r"(a2), "r"(a3), "r"(b0), "r"(b1));
}

__device__ __forceinline__ void bfsplit(float v, uint16_t& h, uint16_t& l) {
    __nv_bfloat16 hb = __float2bfloat16_rn(v);
    float hf = __bfloat162float(hb);
    __nv_bfloat16 lb = __float2bfloat16_rn(v - hf);
    h = *reinterpret_cast<uint16_t*>(&hb);
    l = *reinterpret_cast<uint16_t*>(&lb);
}
__device__ __forceinline__ float bf2f(uint16_t u) {
    return __uint_as_float(((uint32_t)u) << 16);
}

__device__ __forceinline__ uint32_t cvta_s(const void* p) {
    return (uint32_t)__cvta_generic_to_shared(p);
}
__device__ __forceinline__ void ldsm_x4(uint32_t a[4], uint32_t addr) {
    asm volatile("ldmatrix.sync.aligned.m8n8.x4.shared.b16 {%0,%1,%2,%3}, [%4];"
                 : "=r"(a[0]), "=r"(a[1]), "=r"(a[2]), "=r"(a[3]) : "r"(addr));
}
__device__ __forceinline__ uint32_t ldsm_base16(const uint16_t* sA, int lda, int rb, int lane) {
    int m = lane >> 3, r = lane & 7;
    int row = rb + r + ((m & 1) << 3);
    int coff = (m >> 1) << 3;
    return cvta_s(&sA[row * lda + coff]);
}

// ============================================================
// split-bf16 3-term GEMM: ah*bh + ah*bl + al*bh
// ============================================================
template <int MT, int NT, int KS>
__device__ __forceinline__ void gemm4(const uint16_t* sAhi, const uint16_t* sAlo,
                                      int lda, int r0,
                                      const uint4* __restrict__ Bq,
                                      int ldb, int n0, int g, int t, int lane,
                                      float (&acc)[MT][NT][4]) {
    #pragma unroll
    for (int m = 0; m < MT; m++)
        #pragma unroll
        for (int j = 0; j < NT; j++)
            #pragma unroll
            for (int q = 0; q < 4; q++) acc[m][j][q] = 0.f;

    uint32_t bah[MT], bal[MT];
    #pragma unroll
    for (int m = 0; m < MT; m++) {
        bah[m] = ldsm_base16(sAhi, lda, r0 + 16 * m, lane);
        bal[m] = ldsm_base16(sAlo, lda, r0 + 16 * m, lane);
    }
    const uint4* __restrict__ Bbase = Bq + (n0 + g) * 4 + t;

    #pragma unroll 4
    for (int ks = 0; ks < KS; ks++) {
        uint32_t Ah[MT][4], Al[MT][4];
        #pragma unroll
        for (int m = 0; m < MT; m++) {
            ldsm_x4(Ah[m], bah[m] + ks * 32);
            ldsm_x4(Al[m], bal[m] + ks * 32);
        }
        const uint4* __restrict__ Brow = Bbase + ks * ldb * 4;
        #pragma unroll
        for (int j = 0; j < NT; j++) {
            uint4 B = __ldg(Brow + j * 32);
            #pragma unroll
            for (int m = 0; m < MT; m++) {
                mma16(acc[m][j], Ah[m][0], Ah[m][1], Ah[m][2], Ah[m][3], B.x, B.y);
                mma16(acc[m][j], Ah[m][0], Ah[m][1], Ah[m][2], Ah[m][3], B.z, B.w);
                mma16(acc[m][j], Al[m][0], Al[m][1], Al[m][2], Al[m][3], B.x, B.y);
            }
        }
    }
}

// ============================================================
__global__ void k_zero(float* __restrict__ out) {
    int idx = blockIdx.x * 256 + threadIdx.x;
    if (idx < NN) out[idx] = 0.f;
    if (idx < NN * CC) { g_rho0a[idx] = 0.f; g_rho0b[idx] = 0.f; }
    if (idx < NN * CC * 3) { g_rho1a[idx] = 0.f; g_rho1b[idx] = 0.f; }
}

__global__ void k_prep(const float* __restrict__ emb2, const float* __restrict__ wv,
                       const float* __restrict__ wenv, const float* __restrict__ lat1,
                       const float* __restrict__ lat2, const float* __restrict__ wmix) {
    int s = blockIdx.x * 256 + threadIdx.x;
    if (s >= TOTQ) return;
    const float* src; int base, rows, ldb;
    if (s < Q_V)         { src = emb2; base = Q_EMB2; rows = 512; ldb = 64; }
    else if (s < Q_ENV)  { src = wv;   base = Q_V;    rows = 64;  ldb = 64; }
    else if (s < Q_LAT1) { src = wenv; base = Q_ENV;  rows = 64;  ldb = 64; }
    else if (s < Q_LAT2) { src = lat1; base = Q_LAT1; rows = 192; ldb = 512; }
    else if (s < Q_MIX)  { src = lat2; base = Q_LAT2; rows = 512; ldb = 64; }
    else                 { src = wmix; base = Q_MIX;  rows = 64;  ldb = 128; }
    int sl = s - base;
    int mslots = rows * ldb / 4;
    int m = sl / mslots; sl -= m * mslots;
    int t = sl & 3; int tmp = sl >> 2;
    int col = tmp % ldb, kc = tmp / ldb;
    const float* M = src + m * rows * ldb;
    int k0 = kc * 16 + 2 * t;
    float v0 = M[k0 * ldb + col],       v1 = M[(k0 + 1) * ldb + col];
    float v2 = M[(k0 + 8) * ldb + col], v3 = M[(k0 + 9) * ldb + col];
    uint16_t h0, l0, h1, l1, h2, l2, h3, l3;
    bfsplit(v0, h0, l0); bfsplit(v1, h1, l1);
    bfsplit(v2, h2, l2); bfsplit(v3, h3, l3);
    g_Wq[s] = make_uint4(((uint32_t)h1 << 16) | h0, ((uint32_t)h3 << 16) | h2,
                         ((uint32_t)l1 << 16) | l0, ((uint32_t)l3 << 16) | l2);
}

// ============================================================
// K1: embed — 32 edges/block, 256 threads, 2 blocks/SM
// ============================================================
__global__ __launch_bounds__(NTHR, 2) void k_embed(
    const float* __restrict__ pos,
    const int* __restrict__ species,
    const int* __restrict__ senders,
    const int* __restrict__ receivers,
    const float* __restrict__ W1)    // [12,512] fp32
{
    extern __shared__ uint16_t smu[];
    uint16_t* s_hhi = smu;                       // [32][HID_SB]
    uint16_t* s_hlo = s_hhi + TLE * HID_SB;
    uint16_t* s_xhi = s_hlo + TLE * HID_SB;      // [32][XB_S]
    uint16_t* s_xlo = s_xhi + TLE * XB_S;
    float* s_dx = reinterpret_cast<float*>(s_xlo + TLE * XB_S);  // [32][DX_S]
    __shared__ float s_feat[TLE][13];
    __shared__ float s_env[TLE];
    __shared__ float s_u3[TLE * 3];
    __shared__ int   s_send[TLE];

    const int tid = threadIdx.x;
    const int warp = tid >> 5, lane = tid & 31;
    const int g = lane >> 2, t = lane & 3;
    const int e0 = blockIdx.x * TLE;

    // zero dx
    for (int idx = tid; idx < TLE * DX_S; idx += NTHR) s_dx[idx] = 0.f;

    if (tid < TLE) {
        int e = e0 + tid;
        int sn = senders[e], rc = receivers[e];
        s_send[tid] = sn;
        float rx = pos[rc * 3 + 0] - pos[sn * 3 + 0];
        float ry = pos[rc * 3 + 1] - pos[sn * 3 + 1];
        float rz = pos[rc * 3 + 2] - pos[sn * 3 + 2];
        float d = sqrtf(rx * rx + ry * ry + rz * rz);
        float ds = fmaxf(d, 1e-6f);
        float inv = 1.f / ds;
        float ux = rx * inv, uy = ry * inv, uz = rz * inv;
        g_u[e * 3 + 0] = ux; g_u[e * 3 + 1] = uy; g_u[e * 3 + 2] = uz;
        s_u3[tid * 3 + 0] = ux; s_u3[tid * 3 + 1] = uy; s_u3[tid * 3 + 2] = uz;
        float xc = d * 0.5f;
        float env = 0.f;
        if (xc < 1.f) { float tt = 1.f - xc * xc; env = tt * tt; }
        g_env[e] = env;
        s_env[tid] = env;
        float pref = env * inv;
        float ang = PI_F * xc;
        #pragma unroll
        for (int n = 1; n <= 8; n++) s_feat[tid][n - 1] = pref * __sinf((float)n * ang);
        float ssn = (species[sn] == 1) ? 1.f : 0.f;
        float src = (species[rc] == 1) ? 1.f : 0.f;
        s_feat[tid][8] = 1.f - ssn; s_feat[tid][9] = ssn;
        s_feat[tid][10] = 1.f - src; s_feat[tid][11] = src;
    }
    __syncthreads();

    // phase A: hidden = silu(feat @ W1)  (K=12 scalar), 2 cols/thread
    #pragma unroll
    for (int jj = 0; jj < 2; jj++) {
        int h = tid + 256 * jj;
        float w1r[12];
        #pragma unroll
        for (int k = 0; k < 12; k++) w1r[k] = W1[k * HH + h];
        #pragma unroll 4
        for (int i = 0; i < TLE; i++) {
            float acc = 0.f;
            #pragma unroll
            for (int k = 0; k < 12; k++) acc += s_feat[i][k] * w1r[k];
            uint16_t hh, ll;
            bfsplit(silu_f(acc), hh, ll);
            s_hhi[i * HID_SB + h] = hh;
            s_hlo[i * HID_SB + h] = ll;
        }
    }
    __syncthreads();

    // phase B: dx = hidden @ W_emb2, K-split (4 k-slices x 2 N-halves)
    {
        float a2[2][4][4];
        int kw = warp & 3, nh = warp >> 2;
        int n0 = nh * 32;
        gemm4<2, 4, 8>(s_hhi + 128 * kw, s_hlo + 128 * kw, HID_SB, 0,
                       g_Wq + Q_EMB2 + kw * 2048, CC, n0, g, t, lane, a2);
        #pragma unroll
        for (int m = 0; m < 2; m++)
            #pragma unroll
            for (int j = 0; j < 4; j++)
                #pragma unroll
                for (int q = 0; q < 4; q++) {
                    int r = m * 16 + g + ((q & 2) ? 8 : 0);
                    int c = n0 + 8 * j + 2 * t + (q & 1);
                    atomicAdd(&s_dx[r * DX_S + c], a2[m][j][q]);
                }
    }
    __syncthreads();

    // x = dx * env; split into s_x
    #pragma unroll
    for (int q = 0; q < (TLE * CC) / NTHR; q++) {
        int idx = tid + NTHR * q;
        int i = idx >> 6, c = idx & 63;
        float x = s_dx[i * DX_S + c] * s_env[i];
        g_x[(e0 + i) * CC + c] = x;
        uint16_t hh, ll;
        bfsplit(x, hh, ll);
        s_xhi[i * XB_S + c] = hh;
        s_xlo[i * XB_S + c] = ll;
    }
    __syncthreads();

    // vinit: V = (x @ Wv) outer u
    {
        float av[2][1][4];
        int n0 = warp * 8;
        gemm4<2, 1, 4>(s_xhi, s_xlo, XB_S, 0, g_Wq + Q_V, CC, n0, g, t, lane, av);
        #pragma unroll
        for (int m = 0; m < 2; m++)
            #pragma unroll
            for (int q = 0; q < 4; q++) {
                int r = m * 16 + g + ((q & 2) ? 8 : 0);
                int c = n0 + 2 * t + (q & 1);
                float v = av[m][0][q];
                int vb = ((e0 + r) * CC + c) * 3;
                g_V[vb + 0] = v * s_u3[r * 3 + 0];
                g_V[vb + 1] = v * s_u3[r * 3 + 1];
                g_V[vb + 2] = v * s_u3[r * 3 + 2];
            }
    }

    // scatter layer-0 density
    {
        float as[2][1][4];
        int n0 = warp * 8;
        gemm4<2, 1, 4>(s_xhi, s_xlo, XB_S, 0, g_Wq + Q_ENV, CC, n0, g, t, lane, as);
        #pragma unroll
        for (int m = 0; m < 2; m++)
            #pragma unroll
            for (int q = 0; q < 4; q++) {
                int r = m * 16 + g + ((q & 2) ? 8 : 0);
                int c = n0 + 2 * t + (q & 1);
                float v = as[m][0][q] * (1.f / 3.f);
                int sn = s_send[r];
                atomicAdd(&g_rho0a[sn * CC + c], v);
                int rb = (sn * CC + c) * 3;
                atomicAdd(&g_rho1a[rb + 0], v * s_u3[r * 3 + 0]);
                atomicAdd(&g_rho1a[rb + 1], v * s_u3[r * 3 + 1]);
                atomicAdd(&g_rho1a[rb + 2], v * s_u3[r * 3 + 2]);
            }
    }
}

// ============================================================
// K2: full layer — 32 edges/block, 256 threads, 2 blocks/SM
// full hidden, K-split phase-2
// ============================================================
__global__ __launch_bounds__(NTHR, 2) void k_layer(
    int loff1, int loff2, int loffm, int loffe,
    const float* __restrict__ Wout,
    const int* __restrict__ senders,
    const int* __restrict__ receivers,
    const float* __restrict__ rho0r,
    const float* __restrict__ rho1r,
    float* __restrict__ rho0w,
    float* __restrict__ rho1w,
    float* __restrict__ out,
    int mode)
{
    extern __shared__ uint16_t smu[];
    uint16_t* s_lhi = smu;                       // [32][LAT_SB]
    uint16_t* s_llo = s_lhi + TLE * LAT_SB;
    uint16_t* s_hhi = s_llo + TLE * LAT_SB;      // [32][HID_SB]
    uint16_t* s_hlo = s_hhi + TLE * HID_SB;
    float* s_dx  = reinterpret_cast<float*>(s_hlo + TLE * HID_SB);  // [32][DX_S]
    float* s_mix = reinterpret_cast<float*>(s_hhi);  // overlay after phase2
    __shared__ int   s_send[TLE], s_recv[TLE];
    __shared__ float s_env[TLE], s_u3[TLE * 3];

    const int tid = threadIdx.x;
    const int warp = tid >> 5, lane = tid & 31;
    const int g = lane >> 2, t = lane & 3;
    const int e0 = blockIdx.x * TLE;

    // zero dx
    for (int idx = tid; idx < TLE * DX_S; idx += NTHR) s_dx[idx] = 0.f;

    if (tid < TLE) {
        int e = e0 + tid;
        s_send[tid] = senders[e];
        s_recv[tid] = receivers[e];
        s_env[tid] = g_env[e];
        s_u3[tid * 3 + 0] = g_u[e * 3 + 0];
        s_u3[tid * 3 + 1] = g_u[e * 3 + 1];
        s_u3[tid * 3 + 2] = g_u[e * 3 + 2];
    }
    __syncthreads();

    // ---- build split lat_in = [x | tp_scal | rho0_e] ----
    #pragma unroll
    for (int q = 0; q < (TLE * CC) / NTHR; q++) {
        int idx = tid + NTHR * q;
        int i = idx >> 6, c = idx & 63;
        int e = e0 + i, sn = s_send[i];
        float xv = g_x[e * CC + c];
        float r0v = rho0r[sn * CC + c];
        int rb = (sn * CC + c) * 3;
        float r1x = rho1r[rb], r1y = rho1r[rb + 1], r1z = rho1r[rb + 2];
        int vb = (e * CC + c) * 3;
        float Vx = g_V[vb], Vy = g_V[vb + 1], Vz = g_V[vb + 2];
        float tp = Vx * r1x + Vy * r1y + Vz * r1z;
        uint16_t h0, l0, h1, l1, h2, l2;
        bfsplit(xv, h0, l0); bfsplit(tp, h1, l1); bfsplit(r0v, h2, l2);
        s_lhi[i * LAT_SB + c]       = h0;  s_llo[i * LAT_SB + c]       = l0;
        s_lhi[i * LAT_SB + 64 + c]  = h1;  s_llo[i * LAT_SB + 64 + c]  = l1;
        s_lhi[i * LAT_SB + 128 + c] = h2;  s_llo[i * LAT_SB + 128 + c] = l2;
    }
    __syncthreads();

    // ---- phase 1: hidden = silu(lat @ W1), 8 warps x 64 cols, MT=2 NT=8 ----
    {
        float c1[2][8][4];
        int n0 = warp * 64;
        gemm4<2, 8, 12>(s_lhi, s_llo, LAT_SB, 0, g_Wq + loff1, HH, n0, g, t, lane, c1);
        #pragma unroll
        for (int m = 0; m < 2; m++)
            #pragma unroll
            for (int j = 0; j < 8; j++)
                #pragma unroll
                for (int q = 0; q < 4; q++) {
                    int r = m * 16 + g + ((q & 2) ? 8 : 0);
                    int c = n0 + 8 * j + 2 * t + (q & 1);
                    uint16_t hh, ll;
                    bfsplit(silu_f(c1[m][j][q]), hh, ll);
                    s_hhi[r * HID_SB + c] = hh;
                    s_hlo[r * HID_SB + c] = ll;
                }
    }
    __syncthreads();

    // ---- phase 2: dx = hidden @ W2, K-split (4 k-slices x 2 N-halves) ----
    {
        float a2[2][4][4];
        int kw = warp & 3, nh = warp >> 2;
        int n0 = nh * 32;
        gemm4<2, 4, 8>(s_hhi + 128 * kw, s_hlo + 128 * kw, HID_SB, 0,
                       g_Wq + loff2 + kw * 2048, CC, n0, g, t, lane, a2);
        #pragma unroll
        for (int m = 0; m < 2; m++)
            #pragma unroll
            for (int j = 0; j < 4; j++)
                #pragma unroll
                for (int q = 0; q < 4; q++) {
                    int r = m * 16 + g + ((q & 2) ? 8 : 0);
                    int c = n0 + 8 * j + 2 * t + (q & 1);
                    atomicAdd(&s_dx[r * DX_S + c], a2[m][j][q]);
                }
    }
    __syncthreads();

    // ---- x update ----
    const float inv_s2 = 0.70710678118654752f;
    #pragma unroll
    for (int q = 0; q < (TLE * CC) / NTHR; q++) {
        int idx = tid + NTHR * q;
        int i = idx >> 6, c = idx & 63;
        float xo = bf2f(s_lhi[i * LAT_SB + c]) + bf2f(s_llo[i * LAT_SB + c]);
        float xn = (xo + s_dx[i * DX_S + c] * s_env[i]) * inv_s2;
        g_x[(e0 + i) * CC + c] = xn;
        uint16_t hh, ll;
        bfsplit(xn, hh, ll);
        s_lhi[i * LAT_SB + c] = hh;
        s_llo[i * LAT_SB + c] = ll;
    }
    __syncthreads();

    if (mode == 0) {
        // ---- phase 3a: mix = x_new @ Wm (N=128: 8 warps x 16 cols) ----
        {
            float am[2][2][4];
            int n0 = warp * 16;
            gemm4<2, 2, 4>(s_lhi, s_llo, LAT_SB, 0, g_Wq + loffm, 2 * CC, n0, g, t, lane, am);
            __syncthreads();   // s_mix overlays s_hhi
            #pragma unroll
            for (int m = 0; m < 2; m++)
                #pragma unroll
                for (int j = 0; j < 2; j++)
                    #pragma unroll
                    for (int q = 0; q < 4; q++) {
                        int r = m * 16 + g + ((q & 2) ? 8 : 0);
                        int c = n0 + 8 * j + 2 * t + (q & 1);
                        s_mix[r * MIX_S + c] = am[m][j][q];
                    }
        }
        __syncthreads();

        // ---- phase 3b: V = mix1 * (V * rho0) + mix2 * cross(V, rho1) ----
        #pragma unroll
        for (int q = 0; q < (TLE * CC) / NTHR; q++) {
            int idx = tid + NTHR * q;
            int i = idx >> 6, c = idx & 63;
            int e = e0 + i, sn = s_send[i];
            int vb = (e * CC + c) * 3;
            float Vx = g_V[vb], Vy = g_V[vb + 1], Vz = g_V[vb + 2];
            int rb = (sn * CC + c) * 3;
            float r1x = rho1r[rb], r1y = rho1r[rb + 1], r1z = rho1r[rb + 2];
            float r0v = bf2f(s_lhi[i * LAT_SB + 128 + c]) + bf2f(s_llo[i * LAT_SB + 128 + c]);
            float m1 = s_mix[i * MIX_S + c];
            float m2 = s_mix[i * MIX_S + 64 + c];
            float cx = Vy * r1z - Vz * r1y;
            float cy = Vz * r1x - Vx * r1z;
            float cz = Vx * r1y - Vy * r1x;
            g_V[vb + 0] = m1 * Vx * r0v + m2 * cx;
            g_V[vb + 1] = m1 * Vy * r0v + m2 * cy;
            g_V[vb + 2] = m1 * Vz * r0v + m2 * cz;
        }

        // ---- scatter next-layer density (uses x_new) ----
        {
            float as[2][1][4];
            int n0 = warp * 8;
            gemm4<2, 1, 4>(s_lhi, s_llo, LAT_SB, 0, g_Wq + loffe, CC, n0, g, t, lane, as);
            #pragma unroll
            for (int m = 0; m < 2; m++)
                #pragma unroll
                for (int q = 0; q < 4; q++) {
                    int r = m * 16 + g + ((q & 2) ? 8 : 0);
                    int c = n0 + 2 * t + (q & 1);
                    float v = as[m][0][q] * (1.f / 3.f);
                    int sn = s_send[r];
                    atomicAdd(&rho0w[sn * CC + c], v);
                    int rb = (sn * CC + c) * 3;
                    atomicAdd(&rho1w[rb + 0], v * s_u3[r * 3 + 0]);
                    atomicAdd(&rho1w[rb + 1], v * s_u3[r * 3 + 1]);
                    atomicAdd(&rho1w[rb + 2], v * s_u3[r * 3 + 2]);
                }
        }
    } else {
        // ---- final energy readout: 256 threads, 8/row ----
        int i = tid >> 3, k8 = tid & 7;
        float p = 0.f;
        #pragma unroll
        for (int q = 0; q < 8; q++) {
            int c = k8 + 8 * q;
            p += (bf2f(s_lhi[i * LAT_SB + c]) + bf2f(s_llo[i * LAT_SB + c]))
                 * __ldg(&Wout[c]);
        }
        p += __shfl_xor_sync(0xffffffffu, p, 1);
        p += __shfl_xor_sync(0xffffffffu, p, 2);
        p += __shfl_xor_sync(0xffffffffu, p, 4);
        if ((tid & 7) == 0)
            atomicAdd(&out[s_recv[i]], p * s_env[i] * (1.f / 3.f));
    }
}

// ============================================================
extern "C" void kernel_launch(void* const* d_in, const int* in_sizes, int n_in,
                              void* d_out, int out_size)
{
    const float* pos     = (const float*)d_in[0];
    const float* W_emb1  = (const float*)d_in[1];
    const float* W_emb2  = (const float*)d_in[2];
    const float* W_v     = (const float*)d_in[3];
    const float* W_env   = (const float*)d_in[4];
    const float* W_lat1  = (const float*)d_in[5];
    const float* W_lat2  = (const float*)d_in[6];
    const float* W_mix   = (const float*)d_in[7];
    const float* W_out   = (const float*)d_in[8];
    const int*   species = (const int*)d_in[9];
    const int*   senders = (const int*)d_in[10];
    const int*   recv    = (const int*)d_in[11];
    float* out = (float*)d_out;

    const int smem_embed = (2 * TLE * HID_SB + 2 * TLE * XB_S) * 2 + TLE * DX_S * 4;  // 84480
    const int smem_layer = (2 * TLE * LAT_SB + 2 * TLE * HID_SB) * 2 + TLE * DX_S * 4; // 100864
    cudaFuncSetAttribute(k_embed, cudaFuncAttributeMaxDynamicSharedMemorySize, smem_embed);
    cudaFuncSetAttribute(k_layer, cudaFuncAttributeMaxDynamicSharedMemorySize, smem_layer);

    float* rho0a; cudaGetSymbolAddress((void**)&rho0a, g_rho0a);
    float* rho1a; cudaGetSymbolAddress((void**)&rho1a, g_rho1a);
    float* rho0b; cudaGetSymbolAddress((void**)&rho0b, g_rho0b);
    float* rho1b; cudaGetSymbolAddress((void**)&rho1b, g_rho1b);

    k_zero<<<(NN * CC * 3 + 255) / 256, 256>>>(out);
    k_prep<<<(TOTQ + 255) / 256, 256>>>(W_emb2, W_v, W_env, W_lat1, W_lat2, W_mix);
    k_embed<<<NE / TLE, NTHR, smem_embed>>>(pos, species, senders, recv, W_emb1);

    // layer 0: read rhoA, scatter rhoB for layer 1
    k_layer<<<NE / TLE, NTHR, smem_layer>>>(
        Q_LAT1, Q_LAT2, Q_MIX, Q_ENV + 1024, nullptr,
        senders, recv, rho0a, rho1a, rho0b, rho1b, out, 0);
    // layer 1 (final): read rhoB, energy readout
    k_layer<<<NE / TLE, NTHR, smem_layer>>>(
        Q_LAT1 + 24576, Q_LAT2 + 8192, Q_MIX + 2048, 0, W_out,
        senders, recv, rho0b, rho1b, nullptr, nullptr, out, 1);
}

// round 17
// speedup vs baseline: 1.0961x; 1.0588x over previous
#include <cuda_runtime.h>
#include <cuda_bf16.h>
#include <cstdint>
#include <math.h>

#define NE 160000
#define NN 10000
#define CC 64
#define HH 512
#define TLE 32
#define NTHR 256
#define PI_F 3.14159265358979323846f

#define LAT_SB 200
#define HID_SB 520   // embed kernel full-hidden stride
#define HB2    264   // layer kernel half-hidden stride (256+8; 132 words ≡ 4 mod 32)
#define XB_S   72
#define MIX_S  132
#define DX_S   68

// weight quad-slot offsets (uint4 units)
#define Q_EMB2 0
#define Q_V    8192
#define Q_ENV  9216
#define Q_LAT1 11264
#define Q_LAT2 60416
#define Q_MIX  76800
#define TOTQ   80896

__device__ uint4 g_Wq[TOTQ];     // {bh0,bh1,bl0,bl1} bf16x2 fragment quads
__device__ float g_x[NE * CC];
__device__ float g_u[NE * 3];
__device__ float g_env[NE];
__device__ float g_V[NE * CC * 3];
__device__ float g_rho0a[NN * CC];
__device__ float g_rho1a[NN * CC * 3];
__device__ float g_rho0b[NN * CC];
__device__ float g_rho1b[NN * CC * 3];

__device__ __forceinline__ float silu_f(float v) { return v / (1.f + __expf(-v)); }

__device__ __forceinline__ void mma16(float c[4], uint32_t a0, uint32_t a1, uint32_t a2,
                                      uint32_t a3, uint32_t b0, uint32_t b1) {
    asm volatile(
        "mma.sync.aligned.m16n8k16.row.col.f32.bf16.bf16.f32 "
        "{%0,%1,%2,%3},{%4,%5,%6,%7},{%8,%9},{%0,%1,%2,%3};\n"
        : "+f"(c[0]), "+f"(c[1]), "+f"(c[2]), "+f"(c[3])
        : "r"(a0), "r"(a1), "r"(a2), "r"(a3), "r"(b0), "r"(b1));
}

__device__ __forceinline__ void bfsplit(float v, uint16_t& h, uint16_t& l) {
    __nv_bfloat16 hb = __float2bfloat16_rn(v);
    float hf = __bfloat162float(hb);
    __nv_bfloat16 lb = __float2bfloat16_rn(v - hf);
    h = *reinterpret_cast<uint16_t*>(&hb);
    l = *reinterpret_cast<uint16_t*>(&lb);
}
__device__ __forceinline__ float bf2f(uint16_t u) {
    return __uint_as_float(((uint32_t)u) << 16);
}

__device__ __forceinline__ uint32_t cvta_s(const void* p) {
    return (uint32_t)__cvta_generic_to_shared(p);
}
__device__ __forceinline__ void ldsm_x4(uint32_t a[4], uint32_t addr) {
    asm volatile("ldmatrix.sync.aligned.m8n8.x4.shared.b16 {%0,%1,%2,%3}, [%4];"
                 : "=r"(a[0]), "=r"(a[1]), "=r"(a[2]), "=r"(a[3]) : "r"(addr));
}
__device__ __forceinline__ uint32_t ldsm_base16(const uint16_t* sA, int lda, int rb, int lane) {
    int m = lane >> 3, r = lane & 7;
    int row = rb + r + ((m & 1) << 3);
    int coff = (m >> 1) << 3;
    return cvta_s(&sA[row * lda + coff]);
}

// ============================================================
// split-bf16 3-term GEMM: ah*bh + ah*bl + al*bh
// ============================================================
template <int MT, int NT, int KS>
__device__ __forceinline__ void gemm4(const uint16_t* sAhi, const uint16_t* sAlo,
                                      int lda, int r0,
                                      const uint4* __restrict__ Bq,
                                      int ldb, int n0, int g, int t, int lane,
                                      float (&acc)[MT][NT][4]) {
    #pragma unroll
    for (int m = 0; m < MT; m++)
        #pragma unroll
        for (int j = 0; j < NT; j++)
            #pragma unroll
            for (int q = 0; q < 4; q++) acc[m][j][q] = 0.f;

    uint32_t bah[MT], bal[MT];
    #pragma unroll
    for (int m = 0; m < MT; m++) {
        bah[m] = ldsm_base16(sAhi, lda, r0 + 16 * m, lane);
        bal[m] = ldsm_base16(sAlo, lda, r0 + 16 * m, lane);
    }
    const uint4* __restrict__ Bbase = Bq + (n0 + g) * 4 + t;

    #pragma unroll 4
    for (int ks = 0; ks < KS; ks++) {
        uint32_t Ah[MT][4], Al[MT][4];
        #pragma unroll
        for (int m = 0; m < MT; m++) {
            ldsm_x4(Ah[m], bah[m] + ks * 32);
            ldsm_x4(Al[m], bal[m] + ks * 32);
        }
        const uint4* __restrict__ Brow = Bbase + ks * ldb * 4;
        #pragma unroll
        for (int j = 0; j < NT; j++) {
            uint4 B = __ldg(Brow + j * 32);
            #pragma unroll
            for (int m = 0; m < MT; m++) {
                mma16(acc[m][j], Ah[m][0], Ah[m][1], Ah[m][2], Ah[m][3], B.x, B.y);
                mma16(acc[m][j], Ah[m][0], Ah[m][1], Ah[m][2], Ah[m][3], B.z, B.w);
                mma16(acc[m][j], Al[m][0], Al[m][1], Al[m][2], Al[m][3], B.x, B.y);
            }
        }
    }
}

// ============================================================
__global__ void k_zero(float* __restrict__ out) {
    int idx = blockIdx.x * 256 + threadIdx.x;
    if (idx < NN) out[idx] = 0.f;
    if (idx < NN * CC) { g_rho0a[idx] = 0.f; g_rho0b[idx] = 0.f; }
    if (idx < NN * CC * 3) { g_rho1a[idx] = 0.f; g_rho1b[idx] = 0.f; }
}

__global__ void k_prep(const float* __restrict__ emb2, const float* __restrict__ wv,
                       const float* __restrict__ wenv, const float* __restrict__ lat1,
                       const float* __restrict__ lat2, const float* __restrict__ wmix) {
    int s = blockIdx.x * 256 + threadIdx.x;
    if (s >= TOTQ) return;
    const float* src; int base, rows, ldb;
    if (s < Q_V)         { src = emb2; base = Q_EMB2; rows = 512; ldb = 64; }
    else if (s < Q_ENV)  { src = wv;   base = Q_V;    rows = 64;  ldb = 64; }
    else if (s < Q_LAT1) { src = wenv; base = Q_ENV;  rows = 64;  ldb = 64; }
    else if (s < Q_LAT2) { src = lat1; base = Q_LAT1; rows = 192; ldb = 512; }
    else if (s < Q_MIX)  { src = lat2; base = Q_LAT2; rows = 512; ldb = 64; }
    else                 { src = wmix; base = Q_MIX;  rows = 64;  ldb = 128; }
    int sl = s - base;
    int mslots = rows * ldb / 4;
    int m = sl / mslots; sl -= m * mslots;
    int t = sl & 3; int tmp = sl >> 2;
    int col = tmp % ldb, kc = tmp / ldb;
    const float* M = src + m * rows * ldb;
    int k0 = kc * 16 + 2 * t;
    float v0 = M[k0 * ldb + col],       v1 = M[(k0 + 1) * ldb + col];
    float v2 = M[(k0 + 8) * ldb + col], v3 = M[(k0 + 9) * ldb + col];
    uint16_t h0, l0, h1, l1, h2, l2, h3, l3;
    bfsplit(v0, h0, l0); bfsplit(v1, h1, l1);
    bfsplit(v2, h2, l2); bfsplit(v3, h3, l3);
    g_Wq[s] = make_uint4(((uint32_t)h1 << 16) | h0, ((uint32_t)h3 << 16) | h2,
                         ((uint32_t)l1 << 16) | l0, ((uint32_t)l3 << 16) | l2);
}

// ============================================================
// K1: embed — 32 edges/block, 256 threads, 2 blocks/SM
// ============================================================
__global__ __launch_bounds__(NTHR, 2) void k_embed(
    const float* __restrict__ pos,
    const int* __restrict__ species,
    const int* __restrict__ senders,
    const int* __restrict__ receivers,
    const float* __restrict__ W1)    // [12,512] fp32
{
    extern __shared__ uint16_t smu[];
    uint16_t* s_hhi = smu;                       // [32][HID_SB]
    uint16_t* s_hlo = s_hhi + TLE * HID_SB;
    uint16_t* s_xhi = s_hlo + TLE * HID_SB;      // [32][XB_S]
    uint16_t* s_xlo = s_xhi + TLE * XB_S;
    float* s_dx = reinterpret_cast<float*>(s_xlo + TLE * XB_S);  // [32][DX_S]
    __shared__ float s_feat[TLE][13];
    __shared__ float s_env[TLE];
    __shared__ float s_u3[TLE * 3];
    __shared__ int   s_send[TLE];

    const int tid = threadIdx.x;
    const int warp = tid >> 5, lane = tid & 31;
    const int g = lane >> 2, t = lane & 3;
    const int e0 = blockIdx.x * TLE;

    for (int idx = tid; idx < TLE * DX_S; idx += NTHR) s_dx[idx] = 0.f;

    if (tid < TLE) {
        int e = e0 + tid;
        int sn = senders[e], rc = receivers[e];
        s_send[tid] = sn;
        float rx = pos[rc * 3 + 0] - pos[sn * 3 + 0];
        float ry = pos[rc * 3 + 1] - pos[sn * 3 + 1];
        float rz = pos[rc * 3 + 2] - pos[sn * 3 + 2];
        float d = sqrtf(rx * rx + ry * ry + rz * rz);
        float ds = fmaxf(d, 1e-6f);
        float inv = 1.f / ds;
        float ux = rx * inv, uy = ry * inv, uz = rz * inv;
        g_u[e * 3 + 0] = ux; g_u[e * 3 + 1] = uy; g_u[e * 3 + 2] = uz;
        s_u3[tid * 3 + 0] = ux; s_u3[tid * 3 + 1] = uy; s_u3[tid * 3 + 2] = uz;
        float xc = d * 0.5f;
        float env = 0.f;
        if (xc < 1.f) { float tt = 1.f - xc * xc; env = tt * tt; }
        g_env[e] = env;
        s_env[tid] = env;
        float pref = env * inv;
        float ang = PI_F * xc;
        #pragma unroll
        for (int n = 1; n <= 8; n++) s_feat[tid][n - 1] = pref * __sinf((float)n * ang);
        float ssn = (species[sn] == 1) ? 1.f : 0.f;
        float src = (species[rc] == 1) ? 1.f : 0.f;
        s_feat[tid][8] = 1.f - ssn; s_feat[tid][9] = ssn;
        s_feat[tid][10] = 1.f - src; s_feat[tid][11] = src;
    }
    __syncthreads();

    // phase A: hidden = silu(feat @ W1)  (K=12 scalar), 2 cols/thread
    #pragma unroll
    for (int jj = 0; jj < 2; jj++) {
        int h = tid + 256 * jj;
        float w1r[12];
        #pragma unroll
        for (int k = 0; k < 12; k++) w1r[k] = W1[k * HH + h];
        #pragma unroll 4
        for (int i = 0; i < TLE; i++) {
            float acc = 0.f;
            #pragma unroll
            for (int k = 0; k < 12; k++) acc += s_feat[i][k] * w1r[k];
            uint16_t hh, ll;
            bfsplit(silu_f(acc), hh, ll);
            s_hhi[i * HID_SB + h] = hh;
            s_hlo[i * HID_SB + h] = ll;
        }
    }
    __syncthreads();

    // phase B: dx = hidden @ W_emb2, K-split (4 k-slices x 2 N-halves)
    {
        float a2[2][4][4];
        int kw = warp & 3, nh = warp >> 2;
        int n0 = nh * 32;
        gemm4<2, 4, 8>(s_hhi + 128 * kw, s_hlo + 128 * kw, HID_SB, 0,
                       g_Wq + Q_EMB2 + kw * 2048, CC, n0, g, t, lane, a2);
        #pragma unroll
        for (int m = 0; m < 2; m++)
            #pragma unroll
            for (int j = 0; j < 4; j++)
                #pragma unroll
                for (int q = 0; q < 4; q++) {
                    int r = m * 16 + g + ((q & 2) ? 8 : 0);
                    int c = n0 + 8 * j + 2 * t + (q & 1);
                    atomicAdd(&s_dx[r * DX_S + c], a2[m][j][q]);
                }
    }
    __syncthreads();

    // x = dx * env; split into s_x
    #pragma unroll
    for (int q = 0; q < (TLE * CC) / NTHR; q++) {
        int idx = tid + NTHR * q;
        int i = idx >> 6, c = idx & 63;
        float x = s_dx[i * DX_S + c] * s_env[i];
        g_x[(e0 + i) * CC + c] = x;
        uint16_t hh, ll;
        bfsplit(x, hh, ll);
        s_xhi[i * XB_S + c] = hh;
        s_xlo[i * XB_S + c] = ll;
    }
    __syncthreads();

    // vinit: V = (x @ Wv) outer u
    {
        float av[2][1][4];
        int n0 = warp * 8;
        gemm4<2, 1, 4>(s_xhi, s_xlo, XB_S, 0, g_Wq + Q_V, CC, n0, g, t, lane, av);
        #pragma unroll
        for (int m = 0; m < 2; m++)
            #pragma unroll
            for (int q = 0; q < 4; q++) {
                int r = m * 16 + g + ((q & 2) ? 8 : 0);
                int c = n0 + 2 * t + (q & 1);
                float v = av[m][0][q];
                int vb = ((e0 + r) * CC + c) * 3;
                g_V[vb + 0] = v * s_u3[r * 3 + 0];
                g_V[vb + 1] = v * s_u3[r * 3 + 1];
                g_V[vb + 2] = v * s_u3[r * 3 + 2];
            }
    }

    // scatter layer-0 density
    {
        float as[2][1][4];
        int n0 = warp * 8;
        gemm4<2, 1, 4>(s_xhi, s_xlo, XB_S, 0, g_Wq + Q_ENV, CC, n0, g, t, lane, as);
        #pragma unroll
        for (int m = 0; m < 2; m++)
            #pragma unroll
            for (int q = 0; q < 4; q++) {
                int r = m * 16 + g + ((q & 2) ? 8 : 0);
                int c = n0 + 2 * t + (q & 1);
                float v = as[m][0][q] * (1.f / 3.f);
                int sn = s_send[r];
                atomicAdd(&g_rho0a[sn * CC + c], v);
                int rb = (sn * CC + c) * 3;
                atomicAdd(&g_rho1a[rb + 0], v * s_u3[r * 3 + 0]);
                atomicAdd(&g_rho1a[rb + 1], v * s_u3[r * 3 + 1]);
                atomicAdd(&g_rho1a[rb + 2], v * s_u3[r * 3 + 2]);
            }
    }
}

// ============================================================
// K2: full layer — 32 edges/block, 256 threads, 3 blocks/SM
// N-split hidden halves (32x256 buffer), MT=2 tiles throughout
// ============================================================
__global__ __launch_bounds__(NTHR, 3) void k_layer(
    int loff1, int loff2, int loffm, int loffe,
    const float* __restrict__ Wout,
    const int* __restrict__ senders,
    const int* __restrict__ receivers,
    const float* __restrict__ rho0r,
    const float* __restrict__ rho1r,
    float* __restrict__ rho0w,
    float* __restrict__ rho1w,
    float* __restrict__ out,
    int mode)
{
    extern __shared__ uint16_t smu[];
    uint16_t* s_lhi = smu;                       // [32][LAT_SB]
    uint16_t* s_llo = s_lhi + TLE * LAT_SB;
    uint16_t* s_hhi = s_llo + TLE * LAT_SB;      // [32][HB2] half-N hidden
    uint16_t* s_hlo = s_hhi + TLE * HB2;
    float* s_dx  = reinterpret_cast<float*>(s_hlo + TLE * HB2);  // [32][DX_S]
    float* s_mix = reinterpret_cast<float*>(s_hhi);              // overlay after halves
    __shared__ int   s_send[TLE], s_recv[TLE];
    __shared__ float s_env[TLE], s_u3[TLE * 3];

    const int tid = threadIdx.x;
    const int warp = tid >> 5, lane = tid & 31;
    const int g = lane >> 2, t = lane & 3;
    const int e0 = blockIdx.x * TLE;

    for (int idx = tid; idx < TLE * DX_S; idx += NTHR) s_dx[idx] = 0.f;

    if (tid < TLE) {
        int e = e0 + tid;
        s_send[tid] = senders[e];
        s_recv[tid] = receivers[e];
        s_env[tid] = g_env[e];
        s_u3[tid * 3 + 0] = g_u[e * 3 + 0];
        s_u3[tid * 3 + 1] = g_u[e * 3 + 1];
        s_u3[tid * 3 + 2] = g_u[e * 3 + 2];
    }
    __syncthreads();

    // ---- build split lat_in = [x | tp_scal | rho0_e] ----
    #pragma unroll
    for (int q = 0; q < (TLE * CC) / NTHR; q++) {
        int idx = tid + NTHR * q;
        int i = idx >> 6, c = idx & 63;
        int e = e0 + i, sn = s_send[i];
        float xv = g_x[e * CC + c];
        float r0v = rho0r[sn * CC + c];
        int rb = (sn * CC + c) * 3;
        float r1x = rho1r[rb], r1y = rho1r[rb + 1], r1z = rho1r[rb + 2];
        int vb = (e * CC + c) * 3;
        float Vx = g_V[vb], Vy = g_V[vb + 1], Vz = g_V[vb + 2];
        float tp = Vx * r1x + Vy * r1y + Vz * r1z;
        uint16_t h0, l0, h1, l1, h2, l2;
        bfsplit(xv, h0, l0); bfsplit(tp, h1, l1); bfsplit(r0v, h2, l2);
        s_lhi[i * LAT_SB + c]       = h0;  s_llo[i * LAT_SB + c]       = l0;
        s_lhi[i * LAT_SB + 64 + c]  = h1;  s_llo[i * LAT_SB + 64 + c]  = l1;
        s_lhi[i * LAT_SB + 128 + c] = h2;  s_llo[i * LAT_SB + 128 + c] = l2;
    }
    __syncthreads();

    // ---- two N-halves of hidden: phase1 (MT=2 NT=4) + phase2 (K-split) ----
    #pragma unroll 1
    for (int h = 0; h < 2; h++) {
        // phase 1: hidden cols [h*256, h*256+256) = silu(lat @ W1 cols)
        {
            float c1[2][4][4];
            int n0g = h * 256 + warp * 32;        // global W1 column
            gemm4<2, 4, 12>(s_lhi, s_llo, LAT_SB, 0, g_Wq + loff1, HH, n0g, g, t, lane, c1);
            int n0l = warp * 32;                  // local buffer column
            #pragma unroll
            for (int m = 0; m < 2; m++)
                #pragma unroll
                for (int j = 0; j < 4; j++)
                    #pragma unroll
                    for (int q = 0; q < 4; q++) {
                        int r = m * 16 + g + ((q & 2) ? 8 : 0);
                        int c = n0l + 8 * j + 2 * t + (q & 1);
                        uint16_t hh, ll;
                        bfsplit(silu_f(c1[m][j][q]), hh, ll);
                        s_hhi[r * HB2 + c] = hh;
                        s_hlo[r * HB2 + c] = ll;
                    }
        }
        __syncthreads();

        // phase 2: dx += hidden_half @ W2_half, K-split (4 x 64) x 2 N-halves
        {
            float a2[2][4][4];
            int kw = warp & 3, nh = warp >> 2;
            int n0 = nh * 32;
            gemm4<2, 4, 4>(s_hhi + 64 * kw, s_hlo + 64 * kw, HB2, 0,
                           g_Wq + loff2 + (h * 16 + kw * 4) * 256, CC, n0, g, t, lane, a2);
            #pragma unroll
            for (int m = 0; m < 2; m++)
                #pragma unroll
                for (int j = 0; j < 4; j++)
                    #pragma unroll
                    for (int q = 0; q < 4; q++) {
                        int r = m * 16 + g + ((q & 2) ? 8 : 0);
                        int c = n0 + 8 * j + 2 * t + (q & 1);
                        atomicAdd(&s_dx[r * DX_S + c], a2[m][j][q]);
                    }
        }
        __syncthreads();
    }

    // ---- x update ----
    const float inv_s2 = 0.70710678118654752f;
    #pragma unroll
    for (int q = 0; q < (TLE * CC) / NTHR; q++) {
        int idx = tid + NTHR * q;
        int i = idx >> 6, c = idx & 63;
        float xo = bf2f(s_lhi[i * LAT_SB + c]) + bf2f(s_llo[i * LAT_SB + c]);
        float xn = (xo + s_dx[i * DX_S + c] * s_env[i]) * inv_s2;
        g_x[(e0 + i) * CC + c] = xn;
        uint16_t hh, ll;
        bfsplit(xn, hh, ll);
        s_lhi[i * LAT_SB + c] = hh;
        s_llo[i * LAT_SB + c] = ll;
    }
    __syncthreads();

    if (mode == 0) {
        // ---- phase 3a: mix = x_new @ Wm (N=128: 8 warps x 16 cols) ----
        {
            float am[2][2][4];
            int n0 = warp * 16;
            gemm4<2, 2, 4>(s_lhi, s_llo, LAT_SB, 0, g_Wq + loffm, 2 * CC, n0, g, t, lane, am);
            __syncthreads();   // s_mix overlays s_hhi
            #pragma unroll
            for (int m = 0; m < 2; m++)
                #pragma unroll
                for (int j = 0; j < 2; j++)
                    #pragma unroll
                    for (int q = 0; q < 4; q++) {
                        int r = m * 16 + g + ((q & 2) ? 8 : 0);
                        int c = n0 + 8 * j + 2 * t + (q & 1);
                        s_mix[r * MIX_S + c] = am[m][j][q];
                    }
        }
        __syncthreads();

        // ---- phase 3b: V = mix1 * (V * rho0) + mix2 * cross(V, rho1) ----
        #pragma unroll
        for (int q = 0; q < (TLE * CC) / NTHR; q++) {
            int idx = tid + NTHR * q;
            int i = idx >> 6, c = idx & 63;
            int e = e0 + i, sn = s_send[i];
            int vb = (e * CC + c) * 3;
            float Vx = g_V[vb], Vy = g_V[vb + 1], Vz = g_V[vb + 2];
            int rb = (sn * CC + c) * 3;
            float r1x = rho1r[rb], r1y = rho1r[rb + 1], r1z = rho1r[rb + 2];
            float r0v = bf2f(s_lhi[i * LAT_SB + 128 + c]) + bf2f(s_llo[i * LAT_SB + 128 + c]);
            float m1 = s_mix[i * MIX_S + c];
            float m2 = s_mix[i * MIX_S + 64 + c];
            float cx = Vy * r1z - Vz * r1y;
            float cy = Vz * r1x - Vx * r1z;
            float cz = Vx * r1y - Vy * r1x;
            g_V[vb + 0] = m1 * Vx * r0v + m2 * cx;
            g_V[vb + 1] = m1 * Vy * r0v + m2 * cy;
            g_V[vb + 2] = m1 * Vz * r0v + m2 * cz;
        }

        // ---- scatter next-layer density (uses x_new) ----
        {
            float as[2][1][4];
            int n0 = warp * 8;
            gemm4<2, 1, 4>(s_lhi, s_llo, LAT_SB, 0, g_Wq + loffe, CC, n0, g, t, lane, as);
            #pragma unroll
            for (int m = 0; m < 2; m++)
                #pragma unroll
                for (int q = 0; q < 4; q++) {
                    int r = m * 16 + g + ((q & 2) ? 8 : 0);
                    int c = n0 + 2 * t + (q & 1);
                    float v = as[m][0][q] * (1.f / 3.f);
                    int sn = s_send[r];
                    atomicAdd(&rho0w[sn * CC + c], v);
                    int rb = (sn * CC + c) * 3;
                    atomicAdd(&rho1w[rb + 0], v * s_u3[r * 3 + 0]);
                    atomicAdd(&rho1w[rb + 1], v * s_u3[r * 3 + 1]);
                    atomicAdd(&rho1w[rb + 2], v * s_u3[r * 3 + 2]);
                }
        }
    } else {
        // ---- final energy readout: 256 threads, 8/row ----
        int i = tid >> 3, k8 = tid & 7;
        float p = 0.f;
        #pragma unroll
        for (int q = 0; q < 8; q++) {
            int c = k8 + 8 * q;
            p += (bf2f(s_lhi[i * LAT_SB + c]) + bf2f(s_llo[i * LAT_SB + c]))
                 * __ldg(&Wout[c]);
        }
        p += __shfl_xor_sync(0xffffffffu, p, 1);
        p += __shfl_xor_sync(0xffffffffu, p, 2);
        p += __shfl_xor_sync(0xffffffffu, p, 4);
        if ((tid & 7) == 0)
            atomicAdd(&out[s_recv[i]], p * s_env[i] * (1.f / 3.f));
    }
}

// ============================================================
extern "C" void kernel_launch(void* const* d_in, const int* in_sizes, int n_in,
                              void* d_out, int out_size)
{
    const float* pos     = (const float*)d_in[0];
    const float* W_emb1  = (const float*)d_in[1];
    const float* W_emb2  = (const float*)d_in[2];
    const float* W_v     = (const float*)d_in[3];
    const float* W_env   = (const float*)d_in[4];
    const float* W_lat1  = (const float*)d_in[5];
    const float* W_lat2  = (const float*)d_in[6];
    const float* W_mix   = (const float*)d_in[7];
    const float* W_out   = (const float*)d_in[8];
    const int*   species = (const int*)d_in[9];
    const int*   senders = (const int*)d_in[10];
    const int*   recv    = (const int*)d_in[11];
    float* out = (float*)d_out;

    const int smem_embed = (2 * TLE * HID_SB + 2 * TLE * XB_S) * 2 + TLE * DX_S * 4;  // 84480
    const int smem_layer = (2 * TLE * LAT_SB + 2 * TLE * HB2) * 2 + TLE * DX_S * 4;   // 68096
    cudaFuncSetAttribute(k_embed, cudaFuncAttributeMaxDynamicSharedMemorySize, smem_embed);
    cudaFuncSetAttribute(k_layer, cudaFuncAttributeMaxDynamicSharedMemorySize, smem_layer);

    float* rho0a; cudaGetSymbolAddress((void**)&rho0a, g_rho0a);
    float* rho1a; cudaGetSymbolAddress((void**)&rho1a, g_rho1a);
    float* rho0b; cudaGetSymbolAddress((void**)&rho0b, g_rho0b);
    float* rho1b; cudaGetSymbolAddress((void**)&rho1b, g_rho1b);

    k_zero<<<(NN * CC * 3 + 255) / 256, 256>>>(out);
    k_prep<<<(TOTQ + 255) / 256, 256>>>(W_emb2, W_v, W_env, W_lat1, W_lat2, W_mix);
    k_embed<<<NE / TLE, NTHR, smem_embed>>>(pos, species, senders, recv, W_emb1);

    // layer 0: read rhoA, scatter rhoB for layer 1
    k_layer<<<NE / TLE, NTHR, smem_layer>>>(
        Q_LAT1, Q_LAT2, Q_MIX, Q_ENV + 1024, nullptr,
        senders, recv, rho0a, rho1a, rho0b, rho1b, out, 0);
    // layer 1 (final): read rhoB, energy readout
    k_layer<<<NE / TLE, NTHR, smem_layer>>>(
        Q_LAT1 + 24576, Q_LAT2 + 8192, Q_MIX + 2048, 0, W_out,
        senders, recv, rho0b, rho1b, nullptr, nullptr, out, 1);
}